// round 6
// baseline (speedup 1.0000x reference)
#include <cuda_runtime.h>
#include <cuda_fp16.h>
#include <stdint.h>

// ---------------- problem constants ----------------
static constexpr int MROWS = 8192;          // 16*512
static constexpr int FLAT  = 12544;         // 7*7*256
static constexpr int HID   = 1024;
static constexpr int NCLS  = 81;
static constexpr int NPAD  = 128;

// ---------------- scratch (__device__ globals; no allocs allowed) ----------
__device__ __half g_W1t[(size_t)HID * FLAT];   // [N,K] K-major
__device__ __half g_W2t[(size_t)HID * HID];
__device__ __half g_W3t[(size_t)NPAD * HID];   // rows 81..127 zero
__device__ __half g_H1[(size_t)MROWS * HID];
__device__ __half g_H2[(size_t)MROWS * HID];

// ---------------- helpers ----------------
__device__ __forceinline__ uint32_t smem_u32(const void* p) {
    uint32_t a;
    asm("{ .reg .u64 t; cvta.to.shared.u64 t, %1; cvt.u32.u64 %0, t; }" : "=r"(a) : "l"(p));
    return a;
}
#define SWZ(o) ((o) ^ (((o) >> 3) & 0x70))

__device__ __forceinline__ void cp16(uint32_t dst, const void* src) {
    asm volatile("cp.async.cg.shared.global [%0], [%1], 16;" :: "r"(dst), "l"(src) : "memory");
}
__device__ __forceinline__ void cp_commit() { asm volatile("cp.async.commit_group;" ::: "memory"); }
__device__ __forceinline__ void cp_wait1() { asm volatile("cp.async.wait_group 1;" ::: "memory"); }
__device__ __forceinline__ void cp_wait0() { asm volatile("cp.async.wait_group 0;" ::: "memory"); }

__device__ __forceinline__ void ldsm4(uint32_t (&r)[4], uint32_t addr) {
    asm volatile("ldmatrix.sync.aligned.m8n8.x4.shared.b16 {%0,%1,%2,%3}, [%4];"
        : "=r"(r[0]), "=r"(r[1]), "=r"(r[2]), "=r"(r[3]) : "r"(addr));
}
__device__ __forceinline__ void mma16816(float (&d)[4], const uint32_t (&a)[4],
                                         uint32_t b0, uint32_t b1) {
    asm volatile("mma.sync.aligned.m16n8k16.row.col.f32.f16.f16.f32 "
        "{%0,%1,%2,%3}, {%4,%5,%6,%7}, {%8,%9}, {%0,%1,%2,%3};"
        : "+f"(d[0]), "+f"(d[1]), "+f"(d[2]), "+f"(d[3])
        : "r"(a[0]), "r"(a[1]), "r"(a[2]), "r"(a[3]), "r"(b0), "r"(b1));
}

// W[K,N] fp32 -> Wt[Npad,K] fp16 (zero-pad n>=N). grid(Npad/32, K/32), block(32,8)
__global__ void cvt_trans(const float* __restrict__ W, __half* __restrict__ Wt, int K, int N) {
    __shared__ float t[32][33];
    int n0 = blockIdx.x * 32, k0 = blockIdx.y * 32;
    int tx = threadIdx.x, ty = threadIdx.y;
    #pragma unroll
    for (int i = 0; i < 32; i += 8) {
        int n = n0 + tx;
        t[ty + i][tx] = (n < N) ? W[(size_t)(k0 + ty + i) * N + n] : 0.f;
    }
    __syncthreads();
    #pragma unroll
    for (int i = 0; i < 32; i += 8)
        Wt[(size_t)(n0 + ty + i) * K + k0 + tx] = __float2half_rn(t[tx][ty + i]);
}

// ---------------- GEMM1 (fused fp32->fp16 A conversion) ----------------
// C = relu(A32[M,K] @ Wt[N,K]^T + bias) -> fp16, K = FLAT.
// A: LDG fp32 2 chunks ahead into regs, cvt+STS fp16 (2-stage smem).
// B: 3-stage cp.async.  256 threads, 8 warps (2x4), warp tile 64x32.
__global__ void __launch_bounds__(256, 2)
gemm1_f32(const float* __restrict__ A, const __half* __restrict__ Wt,
          const float* __restrict__ bias, __half* __restrict__ outp) {
    constexpr int K = FLAT, KC = K / 64;
    extern __shared__ char smem[];
    const uint32_t sbase = smem_u32(smem);

    const int tid = threadIdx.x, wid = tid >> 5, lid = tid & 31;
    const int m0 = blockIdx.y * 128, n0 = blockIdx.x * 128;
    const int wm = (wid >> 2) * 64, wn = (wid & 3) * 32;

    float acc[4][4][4];
    #pragma unroll
    for (int a = 0; a < 4; ++a)
        #pragma unroll
        for (int b = 0; b < 4; ++b)
            #pragma unroll
            for (int c = 0; c < 4; ++c) acc[a][b][c] = 0.f;

    float4 ra[4][2];
    auto ldgA = [&](int c) {
        #pragma unroll
        for (int i = 0; i < 4; ++i) {
            int op = tid + i * 256, row = op >> 3, seg = op & 7;
            const float4* p = (const float4*)(A + (size_t)(m0 + row) * K + (c << 6) + seg * 8);
            ra[i][0] = p[0]; ra[i][1] = p[1];
        }
    };
    auto stsA = [&](int s) {
        #pragma unroll
        for (int i = 0; i < 4; ++i) {
            int op = tid + i * 256, row = op >> 3, seg = op & 7;
            __half2 h0 = __floats2half2_rn(ra[i][0].x, ra[i][0].y);
            __half2 h1 = __floats2half2_rn(ra[i][0].z, ra[i][0].w);
            __half2 h2 = __floats2half2_rn(ra[i][1].x, ra[i][1].y);
            __half2 h3 = __floats2half2_rn(ra[i][1].z, ra[i][1].w);
            *(uint4*)(smem + s * 16384 + SWZ(row * 128 + seg * 16)) =
                make_uint4(*(uint32_t*)&h0, *(uint32_t*)&h1, *(uint32_t*)&h2, *(uint32_t*)&h3);
        }
    };
    auto ldB = [&](int c) {
        const uint32_t sB = sbase + 32768 + (uint32_t)(c % 3) * 16384;
        const __half* Bb = Wt + (size_t)n0 * K + (c << 6);
        #pragma unroll
        for (int i = 0; i < 4; ++i) {
            int op = tid + i * 256, row = op >> 3, seg = op & 7;
            cp16(sB + SWZ((uint32_t)(row * 128 + seg * 16)), Bb + (size_t)row * K + seg * 8);
        }
        cp_commit();
    };

    ldgA(0); stsA(0);
    ldB(0);
    ldgA(1);
    ldB(1);

    const int lrow = lid & 15, lkh = lid >> 4;
    for (int c = 0; c < KC; ++c) {
        if (c == KC - 1) cp_wait0(); else cp_wait1();
        __syncthreads();
        if (c + 1 < KC) stsA((c + 1) & 1);
        if (c + 2 < KC) { ldgA(c + 2); ldB(c + 2); }
        const uint32_t sA = sbase + (uint32_t)(c & 1) * 16384;
        const uint32_t sB = sbase + 32768 + (uint32_t)(c % 3) * 16384;
        #pragma unroll
        for (int k0 = 0; k0 < 64; k0 += 16) {
            uint32_t bfr[2][4];
            #pragma unroll
            for (int nn = 0; nn < 2; ++nn) {
                uint32_t off = (uint32_t)((wn + nn * 16 + lrow) * 128 + (k0 + lkh * 8) * 2);
                ldsm4(bfr[nn], sB + SWZ(off));
            }
            #pragma unroll
            for (int ms = 0; ms < 4; ++ms) {
                uint32_t afr[4];
                uint32_t off = (uint32_t)((wm + ms * 16 + lrow) * 128 + (k0 + lkh * 8) * 2);
                ldsm4(afr, sA + SWZ(off));
                #pragma unroll
                for (int ns = 0; ns < 4; ++ns)
                    mma16816(acc[ms][ns], afr, bfr[ns >> 1][ns & 1], bfr[ns >> 1][(ns & 1) + 2]);
            }
        }
    }

    #pragma unroll
    for (int ms = 0; ms < 4; ++ms) {
        const int r0 = m0 + wm + ms * 16 + (lid >> 2);
        #pragma unroll
        for (int ns = 0; ns < 4; ++ns) {
            const int col = n0 + wn + ns * 8 + 2 * (lid & 3);
            float bx = bias[col], by = bias[col + 1];
            *(__half2*)(outp + (size_t)r0 * HID + col) =
                __floats2half2_rn(fmaxf(acc[ms][ns][0] + bx, 0.f),
                                  fmaxf(acc[ms][ns][1] + by, 0.f));
            *(__half2*)(outp + (size_t)(r0 + 8) * HID + col) =
                __floats2half2_rn(fmaxf(acc[ms][ns][2] + bx, 0.f),
                                  fmaxf(acc[ms][ns][3] + by, 0.f));
        }
    }
}

// ---------------- HMMA GEMM (fp16 A): C = post(A @ Wt^T + bias) ----------------
// MODE 0: relu, fp16 out (row stride HID).  MODE 1: mask, fp32 out (stride NCLS).
template <int MODE>
__global__ void __launch_bounds__(256, 2)
gemm_hmma(const __half* __restrict__ A, const __half* __restrict__ Wt,
          const float* __restrict__ bias, void* __restrict__ outp,
          const void* __restrict__ maskp, int K) {
    constexpr int A_BYTES = 128 * 128;
    constexpr int STAGE   = A_BYTES + A_BYTES;

    extern __shared__ char smem[];
    const uint32_t tiles = smem_u32(smem);

    const int tid = threadIdx.x, wid = tid >> 5, lid = tid & 31;
    const int m0 = blockIdx.y * 128, n0 = blockIdx.x * 128;
    const int wm = (wid >> 2) * 64, wn = (wid & 3) * 32;
    const int KC = K >> 6;

    float acc[4][4][4];
    #pragma unroll
    for (int a = 0; a < 4; ++a)
        #pragma unroll
        for (int b = 0; b < 4; ++b)
            #pragma unroll
            for (int c = 0; c < 4; ++c) acc[a][b][c] = 0.f;

    auto load_stage = [&](int c) {
        const uint32_t sA = tiles + (uint32_t)(c % 3) * STAGE, sB = sA + A_BYTES;
        const __half* Ab = A + (size_t)m0 * K + (c << 6);
        const __half* Bb = Wt + (size_t)n0 * K + (c << 6);
        #pragma unroll
        for (int i = 0; i < 4; ++i) {
            int op = tid + i * 256, row = op >> 3, seg = op & 7;
            cp16(sA + SWZ((uint32_t)(row * 128 + seg * 16)), Ab + (size_t)row * K + seg * 8);
        }
        #pragma unroll
        for (int i = 0; i < 4; ++i) {
            int op = tid + i * 256, row = op >> 3, seg = op & 7;
            cp16(sB + SWZ((uint32_t)(row * 128 + seg * 16)), Bb + (size_t)row * K + seg * 8);
        }
        cp_commit();
    };

    load_stage(0);
    load_stage(1);

    const int lrow = lid & 15, lkh = lid >> 4;
    for (int c = 0; c < KC; ++c) {
        if (c == KC - 1) cp_wait0(); else cp_wait1();
        __syncthreads();
        if (c + 2 < KC) load_stage(c + 2);
        const uint32_t sA = tiles + (uint32_t)(c % 3) * STAGE, sB = sA + A_BYTES;
        #pragma unroll
        for (int k0 = 0; k0 < 64; k0 += 16) {
            uint32_t bfr[2][4];
            #pragma unroll
            for (int nn = 0; nn < 2; ++nn) {
                uint32_t off = (uint32_t)((wn + nn * 16 + lrow) * 128 + (k0 + lkh * 8) * 2);
                ldsm4(bfr[nn], sB + SWZ(off));
            }
            #pragma unroll
            for (int ms = 0; ms < 4; ++ms) {
                uint32_t afr[4];
                uint32_t off = (uint32_t)((wm + ms * 16 + lrow) * 128 + (k0 + lkh * 8) * 2);
                ldsm4(afr, sA + SWZ(off));
                #pragma unroll
                for (int ns = 0; ns < 4; ++ns)
                    mma16816(acc[ms][ns], afr, bfr[ns >> 1][ns & 1], bfr[ns >> 1][(ns & 1) + 2]);
            }
        }
        __syncthreads();
    }

    int m_is_i8 = 0;
    if (MODE == 1) {
        const unsigned char* m8 = (const unsigned char*)maskp;
        bool i8 = false;
        for (int i = 1; i < 256; ++i)
            if ((i & 3) && m8[i]) i8 = true;
        m_is_i8 = i8 ? 1 : 0;
    }

    #pragma unroll
    for (int ms = 0; ms < 4; ++ms) {
        const int r0 = m0 + wm + ms * 16 + (lid >> 2);
        #pragma unroll
        for (int ns = 0; ns < 4; ++ns) {
            const int col = n0 + wn + ns * 8 + 2 * (lid & 3);
            if (MODE == 0) {
                float bx = bias[col], by = bias[col + 1];
                __half* o = (__half*)outp;
                *(__half2*)(o + (size_t)r0 * HID + col) =
                    __floats2half2_rn(fmaxf(acc[ms][ns][0] + bx, 0.f),
                                      fmaxf(acc[ms][ns][1] + by, 0.f));
                *(__half2*)(o + (size_t)(r0 + 8) * HID + col) =
                    __floats2half2_rn(fmaxf(acc[ms][ns][2] + bx, 0.f),
                                      fmaxf(acc[ms][ns][3] + by, 0.f));
            } else {
                float* o = (float*)outp;
                #pragma unroll
                for (int h = 0; h < 2; ++h) {
                    const int rr = r0 + h * 8;
                    float mv;
                    if (m_is_i8) mv = (((const unsigned char*)maskp)[rr] != 0) ? 1.f : 0.f;
                    else         mv = (((const int*)maskp)[rr] != 0) ? 1.f : 0.f;
                    if (col < NCLS)
                        o[(size_t)rr * NCLS + col] = (acc[ms][ns][2 * h] + bias[col]) * mv;
                    if (col + 1 < NCLS)
                        o[(size_t)rr * NCLS + col + 1] = (acc[ms][ns][2 * h + 1] + bias[col + 1]) * mv;
                }
            }
        }
    }
}

// ---------------- launcher ----------------
extern "C" void kernel_launch(void* const* d_in, const int* in_sizes, int n_in,
                              void* d_out, int out_size) {
    const float* feat = (const float*)d_in[0];
    const void*  mask = d_in[1];
    const float* W1 = (const float*)d_in[2]; const float* b1 = (const float*)d_in[3];
    const float* W2 = (const float*)d_in[4]; const float* b2 = (const float*)d_in[5];
    const float* W3 = (const float*)d_in[6]; const float* b3 = (const float*)d_in[7];

    void *pW1, *pW2, *pW3, *pH1, *pH2;
    cudaGetSymbolAddress(&pW1, g_W1t);
    cudaGetSymbolAddress(&pW2, g_W2t);
    cudaGetSymbolAddress(&pW3, g_W3t);
    cudaGetSymbolAddress(&pH1, g_H1);
    cudaGetSymbolAddress(&pH2, g_H2);

    constexpr int SMEM1 = 2 * 16384 + 3 * 16384;          // 80 KB (gemm1)
    constexpr int SMEM  = 3 * (128 * 128 + 128 * 128);    // 96 KB (gemm2/3)
    cudaFuncSetAttribute(gemm1_f32,   cudaFuncAttributeMaxDynamicSharedMemorySize, SMEM1);
    cudaFuncSetAttribute(gemm_hmma<0>, cudaFuncAttributeMaxDynamicSharedMemorySize, SMEM);
    cudaFuncSetAttribute(gemm_hmma<1>, cudaFuncAttributeMaxDynamicSharedMemorySize, SMEM);

    // weight transposes (fp32 [K,N] -> fp16 [Npad,K])
    cvt_trans<<<dim3(HID / 32, FLAT / 32), dim3(32, 8)>>>(W1, (__half*)pW1, FLAT, HID);
    cvt_trans<<<dim3(HID / 32, HID / 32), dim3(32, 8)>>>(W2, (__half*)pW2, HID, HID);
    cvt_trans<<<dim3(NPAD / 32, HID / 32), dim3(32, 8)>>>(W3, (__half*)pW3, HID, NCLS);
    // MLP
    gemm1_f32<<<dim3(HID / 128, MROWS / 128), 256, SMEM1>>>(
        feat, (const __half*)pW1, b1, (__half*)pH1);
    gemm_hmma<0><<<dim3(HID / 128, MROWS / 128), 256, SMEM>>>(
        (const __half*)pH1, (const __half*)pW2, b2, pH2, nullptr, HID);
    gemm_hmma<1><<<dim3(1, MROWS / 128), 256, SMEM>>>(
        (const __half*)pH2, (const __half*)pW3, b3, d_out, mask, HID);
    (void)in_sizes; (void)n_in; (void)out_size;
}

// round 7
// speedup vs baseline: 1.6971x; 1.6971x over previous
#include <cuda_runtime.h>
#include <cuda_fp16.h>
#include <stdint.h>

// ---------------- problem constants ----------------
static constexpr int MROWS = 8192;          // 16*512
static constexpr int FLAT  = 12544;         // 7*7*256
static constexpr int HID   = 1024;
static constexpr int NCLS  = 81;
static constexpr int NPAD  = 128;

// ---------------- scratch (__device__ globals; no allocs allowed) ----------
__device__ __half g_featH[(size_t)MROWS * FLAT];
__device__ __half g_W1t[(size_t)HID * FLAT];   // [N,K] K-major
__device__ __half g_W2t[(size_t)HID * HID];
__device__ __half g_W3t[(size_t)NPAD * HID];   // rows 81..127 zero
__device__ __half g_H1[(size_t)MROWS * HID];
__device__ __half g_H2[(size_t)MROWS * HID];

// ---------------- helpers ----------------
__device__ __forceinline__ uint32_t smem_u32(const void* p) {
    uint32_t a;
    asm("{ .reg .u64 t; cvta.to.shared.u64 t, %1; cvt.u32.u64 %0, t; }" : "=r"(a) : "l"(p));
    return a;
}
#define SWZ(o) ((o) ^ (((o) >> 3) & 0x70))

__device__ __forceinline__ void cp16(uint32_t dst, const void* src) {
    asm volatile("cp.async.cg.shared.global [%0], [%1], 16;" :: "r"(dst), "l"(src) : "memory");
}
__device__ __forceinline__ void cp_commit() { asm volatile("cp.async.commit_group;" ::: "memory"); }
__device__ __forceinline__ void cp_wait1() { asm volatile("cp.async.wait_group 1;" ::: "memory"); }
__device__ __forceinline__ void cp_wait0() { asm volatile("cp.async.wait_group 0;" ::: "memory"); }

__device__ __forceinline__ void ldsm4(uint32_t (&r)[4], uint32_t addr) {
    asm volatile("ldmatrix.sync.aligned.m8n8.x4.shared.b16 {%0,%1,%2,%3}, [%4];"
        : "=r"(r[0]), "=r"(r[1]), "=r"(r[2]), "=r"(r[3]) : "r"(addr));
}
__device__ __forceinline__ void mma16816(float (&d)[4], const uint32_t (&a)[4],
                                         uint32_t b0, uint32_t b1) {
    asm volatile("mma.sync.aligned.m16n8k16.row.col.f32.f16.f16.f32 "
        "{%0,%1,%2,%3}, {%4,%5,%6,%7}, {%8,%9}, {%0,%1,%2,%3};"
        : "+f"(d[0]), "+f"(d[1]), "+f"(d[2]), "+f"(d[3])
        : "r"(a[0]), "r"(a[1]), "r"(a[2]), "r"(a[3]), "r"(b0), "r"(b1));
}

// ---------------- conversion kernels ----------------
__global__ void cvt_feat(const float4* __restrict__ in, uint2* __restrict__ out, int n4) {
    int i = blockIdx.x * blockDim.x + threadIdx.x;
    if (i < n4) {
        float4 v = in[i];
        __half2 a = __floats2half2_rn(v.x, v.y), b = __floats2half2_rn(v.z, v.w);
        out[i] = make_uint2(*(uint32_t*)&a, *(uint32_t*)&b);
    }
}

// W[K,N] fp32 -> Wt[Npad,K] fp16 (zero-pad n>=N). grid(Npad/32, K/32), block(32,8)
__global__ void cvt_trans(const float* __restrict__ W, __half* __restrict__ Wt, int K, int N) {
    __shared__ float t[32][33];
    int n0 = blockIdx.x * 32, k0 = blockIdx.y * 32;
    int tx = threadIdx.x, ty = threadIdx.y;
    #pragma unroll
    for (int i = 0; i < 32; i += 8) {
        int n = n0 + tx;
        t[ty + i][tx] = (n < N) ? W[(size_t)(k0 + ty + i) * N + n] : 0.f;
    }
    __syncthreads();
    #pragma unroll
    for (int i = 0; i < 32; i += 8)
        Wt[(size_t)(n0 + ty + i) * K + k0 + tx] = __float2half_rn(t[tx][ty + i]);
}

// ---------------- HMMA GEMM: C = post(A[M,K] @ Wt[N,K]^T + bias) ----------------
// BM=128, BN=64, BK=64. 256 threads = 8 warps (4 M x 2 N), warp tile 32x32.
// acc = 32 regs/thread -> 3 CTAs/SM (24 warps) for latency hiding.
// 3-stage cp.async (24 KB/stage).
// MODE 0: relu, fp16 out (row stride HID).  MODE 1: mask, fp32 out (stride NCLS).
template <int MODE>
__global__ void __launch_bounds__(256, 3)
gemm_hmma(const __half* __restrict__ A, const __half* __restrict__ Wt,
          const float* __restrict__ bias, void* __restrict__ outp,
          const void* __restrict__ maskp, int K) {
    constexpr int A_BYTES = 128 * 128;   // 128 rows x 64 halves
    constexpr int B_BYTES = 64 * 128;    // 64 rows x 64 halves
    constexpr int STAGE   = A_BYTES + B_BYTES;   // 24 KB

    extern __shared__ char smem[];
    const uint32_t tiles = smem_u32(smem);

    const int tid = threadIdx.x, wid = tid >> 5, lid = tid & 31;
    const int m0 = blockIdx.y * 128, n0 = blockIdx.x * 64;
    const int wm = (wid >> 1) * 32, wn = (wid & 1) * 32;
    const int KC = K >> 6;

    float acc[2][4][4];
    #pragma unroll
    for (int a = 0; a < 2; ++a)
        #pragma unroll
        for (int b = 0; b < 4; ++b)
            #pragma unroll
            for (int c = 0; c < 4; ++c) acc[a][b][c] = 0.f;

    auto load_stage = [&](int c) {
        const uint32_t sA = tiles + (uint32_t)(c % 3) * STAGE, sB = sA + A_BYTES;
        const __half* Ab = A + (size_t)m0 * K + (c << 6);
        const __half* Bb = Wt + (size_t)n0 * K + (c << 6);
        #pragma unroll
        for (int i = 0; i < 4; ++i) {          // A: 1024 16B-ops
            int op = tid + i * 256, row = op >> 3, seg = op & 7;
            cp16(sA + SWZ((uint32_t)(row * 128 + seg * 16)), Ab + (size_t)row * K + seg * 8);
        }
        #pragma unroll
        for (int i = 0; i < 2; ++i) {          // B: 512 16B-ops
            int op = tid + i * 256, row = op >> 3, seg = op & 7;
            cp16(sB + SWZ((uint32_t)(row * 128 + seg * 16)), Bb + (size_t)row * K + seg * 8);
        }
        cp_commit();
    };

    load_stage(0);
    load_stage(1);

    const int lrow = lid & 15, lkh = lid >> 4;
    for (int c = 0; c < KC; ++c) {
        if (c == KC - 1) cp_wait0(); else cp_wait1();
        __syncthreads();
        if (c + 2 < KC) load_stage(c + 2);
        const uint32_t sA = tiles + (uint32_t)(c % 3) * STAGE, sB = sA + A_BYTES;
        #pragma unroll
        for (int k0 = 0; k0 < 64; k0 += 16) {
            uint32_t bfr[2][4];
            #pragma unroll
            for (int nn = 0; nn < 2; ++nn) {
                uint32_t off = (uint32_t)((wn + nn * 16 + lrow) * 128 + (k0 + lkh * 8) * 2);
                ldsm4(bfr[nn], sB + SWZ(off));
            }
            #pragma unroll
            for (int ms = 0; ms < 2; ++ms) {
                uint32_t afr[4];
                uint32_t off = (uint32_t)((wm + ms * 16 + lrow) * 128 + (k0 + lkh * 8) * 2);
                ldsm4(afr, sA + SWZ(off));
                #pragma unroll
                for (int ns = 0; ns < 4; ++ns)
                    mma16816(acc[ms][ns], afr, bfr[ns >> 1][ns & 1], bfr[ns >> 1][(ns & 1) + 2]);
            }
        }
        __syncthreads();
    }

    int m_is_i8 = 0;
    if (MODE == 1) {
        const unsigned char* m8 = (const unsigned char*)maskp;
        bool i8 = false;
        for (int i = 1; i < 256; ++i)
            if ((i & 3) && m8[i]) i8 = true;
        m_is_i8 = i8 ? 1 : 0;
    }

    #pragma unroll
    for (int ms = 0; ms < 2; ++ms) {
        const int r0 = m0 + wm + ms * 16 + (lid >> 2);
        #pragma unroll
        for (int ns = 0; ns < 4; ++ns) {
            const int col = n0 + wn + ns * 8 + 2 * (lid & 3);
            if (MODE == 0) {
                float bx = bias[col], by = bias[col + 1];
                __half* o = (__half*)outp;
                *(__half2*)(o + (size_t)r0 * HID + col) =
                    __floats2half2_rn(fmaxf(acc[ms][ns][0] + bx, 0.f),
                                      fmaxf(acc[ms][ns][1] + by, 0.f));
                *(__half2*)(o + (size_t)(r0 + 8) * HID + col) =
                    __floats2half2_rn(fmaxf(acc[ms][ns][2] + bx, 0.f),
                                      fmaxf(acc[ms][ns][3] + by, 0.f));
            } else {
                float* o = (float*)outp;
                #pragma unroll
                for (int h = 0; h < 2; ++h) {
                    const int rr = r0 + h * 8;
                    float mv;
                    if (m_is_i8) mv = (((const unsigned char*)maskp)[rr] != 0) ? 1.f : 0.f;
                    else         mv = (((const int*)maskp)[rr] != 0) ? 1.f : 0.f;
                    if (col < NCLS)
                        o[(size_t)rr * NCLS + col] = (acc[ms][ns][2 * h] + bias[col]) * mv;
                    if (col + 1 < NCLS)
                        o[(size_t)rr * NCLS + col + 1] = (acc[ms][ns][2 * h + 1] + bias[col + 1]) * mv;
                }
            }
        }
    }
}

// ---------------- launcher ----------------
extern "C" void kernel_launch(void* const* d_in, const int* in_sizes, int n_in,
                              void* d_out, int out_size) {
    const float* feat = (const float*)d_in[0];
    const void*  mask = d_in[1];
    const float* W1 = (const float*)d_in[2]; const float* b1 = (const float*)d_in[3];
    const float* W2 = (const float*)d_in[4]; const float* b2 = (const float*)d_in[5];
    const float* W3 = (const float*)d_in[6]; const float* b3 = (const float*)d_in[7];

    void *pF, *pW1, *pW2, *pW3, *pH1, *pH2;
    cudaGetSymbolAddress(&pF,  g_featH);
    cudaGetSymbolAddress(&pW1, g_W1t);
    cudaGetSymbolAddress(&pW2, g_W2t);
    cudaGetSymbolAddress(&pW3, g_W3t);
    cudaGetSymbolAddress(&pH1, g_H1);
    cudaGetSymbolAddress(&pH2, g_H2);

    constexpr int SMEM = 3 * (128 * 128 + 64 * 128);   // 72 KB
    cudaFuncSetAttribute(gemm_hmma<0>, cudaFuncAttributeMaxDynamicSharedMemorySize, SMEM);
    cudaFuncSetAttribute(gemm_hmma<1>, cudaFuncAttributeMaxDynamicSharedMemorySize, SMEM);

    // 1) features fp32 -> fp16
    int n4 = MROWS * FLAT / 4;
    cvt_feat<<<(n4 + 255) / 256, 256>>>((const float4*)feat, (uint2*)pF, n4);
    // 2) weight transposes (fp32 [K,N] -> fp16 [Npad,K])
    cvt_trans<<<dim3(HID / 32, FLAT / 32), dim3(32, 8)>>>(W1, (__half*)pW1, FLAT, HID);
    cvt_trans<<<dim3(HID / 32, HID / 32), dim3(32, 8)>>>(W2, (__half*)pW2, HID, HID);
    cvt_trans<<<dim3(NPAD / 32, HID / 32), dim3(32, 8)>>>(W3, (__half*)pW3, HID, NCLS);
    // 3) MLP  (grid.x = N-tiles so concurrent CTAs share A-tiles in L2)
    gemm_hmma<0><<<dim3(HID / 64, MROWS / 128), 256, SMEM>>>(
        (const __half*)pF, (const __half*)pW1, b1, pH1, nullptr, FLAT);
    gemm_hmma<0><<<dim3(HID / 64, MROWS / 128), 256, SMEM>>>(
        (const __half*)pH1, (const __half*)pW2, b2, pH2, nullptr, HID);
    gemm_hmma<1><<<dim3(NPAD / 64, MROWS / 128), 256, SMEM>>>(
        (const __half*)pH2, (const __half*)pW3, b3, d_out, mask, HID);
    (void)in_sizes; (void)n_in; (void)out_size;
}